// round 9
// baseline (speedup 1.0000x reference)
#include <cuda_runtime.h>

// AbstractRelu (DeepPoly ReLU relaxation), elementwise over N fp32.
// out layout: [relu(x) (N)] [lb_slope*low (N)] [relu(high) (N)]
//
// R9: final granularity probe — identical per-thread code to the best
// config (R5/R8: 1 float4 quad/thread, sequential loads, .cs hints),
// block size 64 (grid 65536, 32 CTAs/SM, same 2048 threads/SM occupancy).
// History: R2 front-batch 65.6 (regr), R4 persistent 71.7 (regr),
// R7 v8 ld/st 64.2 (neutral), R6 2-quad 63.8 (neutral),
// R1/R3 256t 63.6, R5/R8 128t 63.26 = best. Kernel is HBM-bound at
// ~7.25 TB/s effective (~91% of spec); traffic is at the 402MB floor.

__global__ void __launch_bounds__(64, 32)
abstract_relu_kernel(const float4* __restrict__ x,
                     const float4* __restrict__ low,
                     const float4* __restrict__ high,
                     float4* __restrict__ x_out,
                     float4* __restrict__ low_out,
                     float4* __restrict__ high_out,
                     int n4)
{
    int i = blockIdx.x * blockDim.x + threadIdx.x;
    if (i >= n4) return;

    float4 xv = __ldcs(&x[i]);
    float4 lv = __ldcs(&low[i]);
    float4 hv = __ldcs(&high[i]);

    float4 xo, lo, ho;

    #define LANE(f)                                                        \
    {                                                                      \
        float xe = xv.f, le = lv.f, he = hv.f;                             \
        xo.f = fmaxf(xe, 0.0f);                                            \
        ho.f = fmaxf(he, 0.0f);                                            \
        bool zero = (he <= 0.0f) || (le < 0.0f && le * le > he * he);      \
        lo.f = zero ? 0.0f : le;                                           \
    }

    LANE(x) LANE(y) LANE(z) LANE(w)
    #undef LANE

    __stcs(&x_out[i],    xo);
    __stcs(&low_out[i],  lo);
    __stcs(&high_out[i], ho);
}

extern "C" void kernel_launch(void* const* d_in, const int* in_sizes, int n_in,
                              void* d_out, int out_size)
{
    const float* x    = (const float*)d_in[0];
    const float* low  = (const float*)d_in[1];
    const float* high = (const float*)d_in[2];
    float* out = (float*)d_out;

    const int n  = in_sizes[0];          // 16777216
    const int n4 = n / 4;                // 4194304

    float* x_out    = out;
    float* low_out  = out + n;
    float* high_out = out + 2 * (size_t)n;

    const int threads = 64;
    const int blocks  = (n4 + threads - 1) / threads;  // 65536

    abstract_relu_kernel<<<blocks, threads>>>(
        (const float4*)x, (const float4*)low, (const float4*)high,
        (float4*)x_out, (float4*)low_out, (float4*)high_out, n4);
}